// round 8
// baseline (speedup 1.0000x reference)
#include <cuda_runtime.h>
#include <cstdint>

#define Gn 128
#define Sn 32
#define Nn 32
#define Dn 128
#define Ln 3
#define Hn 4
#define HDn 32
#define Tn (Gn*Sn*Nn)        // 131072
#define TOn (Gn*Nn)          // 4096
#define En 1048576
#define EOn 16384
#define NTASK 10
#define EPSn 1e-5f

// ---------------- device scratch (allocation-free) ----------------
__device__ float g_x[Tn*Dn];
__device__ float g_agg1[Tn*Dn];
__device__ float g_c1[Tn*Dn];
__device__ float g_sub[Gn*Sn*Dn];
__device__ float g_q[Gn*Sn*Dn];
__device__ float g_k[Gn*Sn*Dn];
__device__ float g_attn[Gn*Sn*Sn];
__device__ float g_xatt[TOn*Dn];
__device__ float g_agg2[TOn*Dn];
__device__ float g_c2[TOn*Dn];
__device__ float g_h2[TOn*Dn];
__device__ float g_acc[512];
// combined CSR scratch (big graph at base 0 / En, original graph at base Tn / En)
__device__ int g_degs[Tn + TOn];
__device__ int g_offs[Tn + 1 + TOn + 1];
__device__ int g_curs[Tn + TOn];
__device__ int g_srcs_all[En + EOn];

// ---------------- CSR build (combined for both graphs) ----------------
__global__ void hist_both(const int* __restrict__ dstBig, const int* __restrict__ dstSmall,
                          int* __restrict__ degs)
{
    int e = blockIdx.x * blockDim.x + threadIdx.x;
    if (e < En) {
        atomicAdd(&degs[__ldg(&dstBig[e])], 1);
    } else if (e < En + EOn) {
        atomicAdd(&degs[Tn + __ldg(&dstSmall[e - En])], 1);
    }
}

// 2 blocks: block 0 scans big graph (Tn), block 1 scans small graph (TOn)
__global__ __launch_bounds__(1024)
void scan_both(const int* __restrict__ degs, int* __restrict__ offs, int* __restrict__ curs)
{
    __shared__ int part[1024];
    const int t = threadIdx.x;
    const int n = (blockIdx.x == 0) ? Tn : TOn;
    const int dbase = (blockIdx.x == 0) ? 0 : Tn;
    const int obase = (blockIdx.x == 0) ? 0 : (Tn + 1);
    const int chunk = n / 1024;
    const int base = t * chunk;
    int s = 0;
    for (int i = 0; i < chunk; i++) s += degs[dbase + base + i];
    part[t] = s;
    __syncthreads();
    for (int d = 1; d < 1024; d <<= 1) {
        int v = (t >= d) ? part[t - d] : 0;
        __syncthreads();
        part[t] += v;
        __syncthreads();
    }
    int run = (t > 0) ? part[t - 1] : 0;
    for (int i = 0; i < chunk; i++) {
        offs[obase + base + i] = run;
        curs[dbase + base + i] = run;
        run += degs[dbase + base + i];
    }
    if (t == 1023) offs[obase + n] = run;
}

__global__ void fill_both(const int* __restrict__ ei, const int* __restrict__ oei,
                          int* __restrict__ curs, int* __restrict__ srcs_all)
{
    int e = blockIdx.x * blockDim.x + threadIdx.x;
    if (e < En) {
        int d = __ldg(&ei[En + e]);              // dst
        int pos = atomicAdd(&curs[d], 1);
        srcs_all[pos] = __ldg(&ei[e]);           // src
    } else if (e < En + EOn) {
        int eo = e - En;
        int d = __ldg(&oei[EOn + eo]);
        int pos = atomicAdd(&curs[Tn + d], 1);
        srcs_all[En + pos] = __ldg(&oei[eo]);
    }
}

// ---------------- CSR gather: warp per node, float4 per lane, non-atomic ----------------
// If accZero != nullptr, block 0 zeroes accZero[0:512] (BN1+BN2 stats accumulator).
__global__ void gather_kernel(const float* __restrict__ x, const int* __restrict__ off,
                              const int* __restrict__ srcs, float* __restrict__ agg,
                              int nNodes, float* __restrict__ accZero)
{
    if (accZero && blockIdx.x == 0) {
        accZero[threadIdx.x] = 0.f;
        accZero[threadIdx.x + 256] = 0.f;
    }
    int node = (blockIdx.x * blockDim.x + threadIdx.x) >> 5;
    int lane = threadIdx.x & 31;
    if (node >= nNodes) return;
    int e0 = __ldg(&off[node]);
    int e1 = __ldg(&off[node + 1]);
    float4 a0 = make_float4(0.f, 0.f, 0.f, 0.f);
    float4 a1 = make_float4(0.f, 0.f, 0.f, 0.f);
    int e = e0;
    for (; e + 1 < e1; e += 2) {
        int sA = __ldg(&srcs[e]);
        int sB = __ldg(&srcs[e + 1]);
        float4 va = __ldg(((const float4*)(x + (size_t)sA * Dn)) + lane);
        float4 vb = __ldg(((const float4*)(x + (size_t)sB * Dn)) + lane);
        a0.x += va.x; a0.y += va.y; a0.z += va.z; a0.w += va.w;
        a1.x += vb.x; a1.y += vb.y; a1.z += vb.z; a1.w += vb.w;
    }
    if (e < e1) {
        int sA = __ldg(&srcs[e]);
        float4 va = __ldg(((const float4*)(x + (size_t)sA * Dn)) + lane);
        a0.x += va.x; a0.y += va.y; a0.z += va.z; a0.w += va.w;
    }
    a0.x += a1.x; a0.y += a1.y; a0.z += a1.z; a0.w += a1.w;
    ((float4*)(agg + (size_t)node * Dn))[lane] = a0;
}

// ---------------- cp.async helpers ----------------
__device__ __forceinline__ void cpasync16(void* dst, const void* src)
{
    uint32_t d = (uint32_t)__cvta_generic_to_shared(dst);
    asm volatile("cp.async.cg.shared.global [%0], [%1], 16;" :: "r"(d), "l"(src));
}
__device__ __forceinline__ void cpasync_commit() { asm volatile("cp.async.commit_group;"); }
template<int N> __device__ __forceinline__ void cpasync_wait() { asm volatile("cp.async.wait_group %0;" :: "n"(N)); }

// ---------------- tf32 tensor-core GEMM: C = A1@W1 (+ A2@W2) + bias ----------------
// 128x128 tile, BK=16, 2-stage static-smem double buffer (R5-proven shape),
// 256 threads (8 warps 2x4), warp tile 64x32 via m16n8k8.
// Raw fp32 bits fed as tf32 (truncation; no cvt in hot loop).
// blockIdx.y==1 selects alternate (W1b, biasb, Cb) operand set (Q/K fusion).
#define ASTR 20
#define BSTR 136
#define A_ST (128 * ASTR)
#define B_ST (16 * BSTR)
__global__ __launch_bounds__(256)
void conv_gemm_tf32(const float* __restrict__ A1, const float* __restrict__ A2,
                    const float* __restrict__ W1in, const float* __restrict__ W2,
                    const float* __restrict__ biasin, float* __restrict__ Cin,
                    float* __restrict__ statAcc,
                    const float* __restrict__ W1b, const float* __restrict__ biasb,
                    float* __restrict__ Cb)
{
    __shared__ float As[2 * A_ST];
    __shared__ float Bs[2 * B_ST];

    const float* W1 = (blockIdx.y == 0) ? W1in : W1b;
    const float* bias = (blockIdx.y == 0) ? biasin : biasb;
    float* C = (blockIdx.y == 0) ? Cin : Cb;

    const int tid = threadIdx.x;
    const int wid = tid >> 5, lane = tid & 31;
    const int wm = wid >> 2, wn = wid & 3;
    const int group = lane >> 2, tig = lane & 3;
    const int row0 = blockIdx.x * 128;
    const int nst = (A2 != nullptr) ? 16 : 8;

    float acc[4][4][4];
#pragma unroll
    for (int i = 0; i < 4; i++)
#pragma unroll
        for (int j = 0; j < 4; j++)
#pragma unroll
            for (int r = 0; r < 4; r++) acc[i][j][r] = 0.f;

    auto load_stage = [&](int kt) {
        const float* A = (kt >= 8) ? A2 : A1;
        const float* W = (kt >= 8) ? W2 : W1;
        const int kg = (kt & 7) * 16;
        float* as = As + (kt & 1) * A_ST;
        float* bs = Bs + (kt & 1) * B_ST;
#pragma unroll
        for (int p = 0; p < 2; p++) {
            int f = tid + p * 256;
            int row = f >> 2, kq = f & 3;
            cpasync16(as + row * ASTR + kq * 4,
                      A + (size_t)(row0 + row) * Dn + kg + kq * 4);
        }
#pragma unroll
        for (int p = 0; p < 2; p++) {
            int f = tid + p * 256;
            int row = f >> 5, nq = f & 31;
            cpasync16(bs + row * BSTR + nq * 4,
                      W + (size_t)(kg + row) * Dn + nq * 4);
        }
        cpasync_commit();
    };

    load_stage(0);
    for (int s = 0; s < nst; s++) {
        if (s + 1 < nst) { load_stage(s + 1); cpasync_wait<1>(); }
        else             { cpasync_wait<0>(); }
        __syncthreads();

        const uint32_t* sa = (const uint32_t*)(As + (s & 1) * A_ST);
        const uint32_t* sb = (const uint32_t*)(Bs + (s & 1) * B_ST);
#pragma unroll
        for (int ks = 0; ks < 2; ks++) {
            const int k0 = ks * 8;
            uint32_t ua[4][4], ub[4][2];
#pragma unroll
            for (int i = 0; i < 4; i++) {
                int r = wm * 64 + i * 16 + group;
                ua[i][0] = sa[r * ASTR + k0 + tig];
                ua[i][1] = sa[(r + 8) * ASTR + k0 + tig];
                ua[i][2] = sa[r * ASTR + k0 + 4 + tig];
                ua[i][3] = sa[(r + 8) * ASTR + k0 + 4 + tig];
            }
#pragma unroll
            for (int j = 0; j < 4; j++) {
                int n = wn * 32 + j * 8 + group;
                ub[j][0] = sb[(k0 + tig) * BSTR + n];
                ub[j][1] = sb[(k0 + 4 + tig) * BSTR + n];
            }
#pragma unroll
            for (int i = 0; i < 4; i++)
#pragma unroll
                for (int j = 0; j < 4; j++) {
                    asm volatile(
                        "mma.sync.aligned.m16n8k8.row.col.f32.tf32.tf32.f32 "
                        "{%0,%1,%2,%3}, {%4,%5,%6,%7}, {%8,%9}, {%0,%1,%2,%3};"
                        : "+f"(acc[i][j][0]), "+f"(acc[i][j][1]),
                          "+f"(acc[i][j][2]), "+f"(acc[i][j][3])
                        : "r"(ua[i][0]), "r"(ua[i][1]), "r"(ua[i][2]), "r"(ua[i][3]),
                          "r"(ub[j][0]), "r"(ub[j][1]));
                }
        }
        __syncthreads();
    }

#pragma unroll
    for (int j = 0; j < 4; j++) {
        const int n = wn * 32 + j * 8 + tig * 2;
        const float bv0 = __ldg(&bias[n]);
        const float bv1 = __ldg(&bias[n + 1]);
        float s0 = 0.f, s1 = 0.f, q0 = 0.f, q1 = 0.f;
#pragma unroll
        for (int i = 0; i < 4; i++) {
            const int row = row0 + wm * 64 + i * 16 + group;
            float v0 = acc[i][j][0] + bv0;
            float v1 = acc[i][j][1] + bv1;
            float v2 = acc[i][j][2] + bv0;
            float v3 = acc[i][j][3] + bv1;
            *(float2*)(C + (size_t)row * Dn + n)       = make_float2(v0, v1);
            *(float2*)(C + (size_t)(row + 8) * Dn + n) = make_float2(v2, v3);
            s0 += v0 + v2;  q0 += v0 * v0 + v2 * v2;
            s1 += v1 + v3;  q1 += v1 * v1 + v3 * v3;
        }
        if (statAcc) {
#pragma unroll
            for (int off = 4; off <= 16; off <<= 1) {
                s0 += __shfl_down_sync(0xffffffffu, s0, off);
                s1 += __shfl_down_sync(0xffffffffu, s1, off);
                q0 += __shfl_down_sync(0xffffffffu, q0, off);
                q1 += __shfl_down_sync(0xffffffffu, q1, off);
            }
            if (group == 0) {
                atomicAdd(&statAcc[n], s0);
                atomicAdd(&statAcc[Dn + n], q0);
                atomicAdd(&statAcc[n + 1], s1);
                atomicAdd(&statAcc[Dn + n + 1], q1);
            }
        }
    }
}

// ---------------- BN2: prep folded into apply ----------------
__global__ void bn_apply2(const float* __restrict__ c, const float* __restrict__ acc,
                          const float* __restrict__ gamma, const float* __restrict__ beta,
                          float* __restrict__ h)
{
    int idx = blockIdx.x * blockDim.x + threadIdx.x;
    if (idx >= TOn * Dn) return;
    int d = idx & (Dn - 1);
    float mu = acc[d] * (1.f / TOn);
    float var = acc[Dn + d] * (1.f / TOn) - mu * mu;
    float sc = gamma[d] * rsqrtf(var + EPSn);
    float sh = beta[d] - mu * sc;
    h[idx] = sc * c[idx] + sh;
}

// ---------------- sub = mean over N (layer 0 only) ----------------
__global__ void submean_kernel(const float* __restrict__ x, float* __restrict__ sub)
{
    int b = blockIdx.x;
    int d = threadIdx.x;
    const float* xp = x + (size_t)b * Nn * Dn;
    float s = 0.f;
#pragma unroll 8
    for (int n = 0; n < Nn; n++) s += xp[n * Dn + d];
    sub[(size_t)b * Dn + d] = s * (1.f / Nn);
}

// ---------------- fused attention + weighted reassembly ----------------
__global__ __launch_bounds__(256)
void attn_xatten_kernel(const float* __restrict__ q, const float* __restrict__ k,
                        const float* __restrict__ x,
                        float* __restrict__ attn, float* __restrict__ xatt)
{
    int g = blockIdx.x;
    int tid = threadIdx.x;              // 256
    __shared__ float qs[Dn * 33];       // transposed [c][qi], stride 33
    __shared__ float ks[Sn * Dn];
    __shared__ float at[Sn * Sn];
    const float* qg = q + (size_t)g * Sn * Dn;
    const float* kg = k + (size_t)g * Sn * Dn;
    for (int i = tid; i < Sn * Dn; i += 256) {
        int qi = i >> 7, c = i & 127;
        qs[c * 33 + qi] = qg[i];
        ks[i] = kg[i];
    }
    for (int i = tid; i < Sn * Sn; i += 256) at[i] = 0.f;
    __syncthreads();

    if (tid < 128) {
        int h = tid >> 5;
        int qi = tid & 31;
        const float scale = 0.17677669529663687f;  // 1/sqrt(32)
        float sc[Sn];
        float mx = -1e30f;
#pragma unroll
        for (int j = 0; j < Sn; j++) {
            float dsum = 0.f;
#pragma unroll
            for (int hd = 0; hd < HDn; hd++)
                dsum += qs[(h * HDn + hd) * 33 + qi] * ks[j * Dn + h * HDn + hd];
            sc[j] = dsum * scale;
            mx = fmaxf(mx, sc[j]);
        }
        float se = 0.f;
#pragma unroll
        for (int j = 0; j < Sn; j++) { sc[j] = expf(sc[j] - mx); se += sc[j]; }
        float inv = 0.25f / se;   // head-mean folded in
#pragma unroll
        for (int j = 0; j < Sn; j++) atomicAdd(&at[qi * Sn + j], sc[j] * inv);
    }
    __syncthreads();

    for (int i = tid; i < Sn * Sn; i += 256) attn[(size_t)g * Sn * Sn + i] = at[i];

    const float* xg = x + (size_t)g * Sn * Nn * Dn;
    for (int idx = tid; idx < Nn * Dn; idx += 256) {
        int n = idx >> 7, d = idx & 127;
        float acc = 0.f;
#pragma unroll 8
        for (int s = 0; s < Sn; s++)
            acc += at[s * Sn + n] * xg[(size_t)(s * Nn + n) * Dn + d];
        xatt[(size_t)(g * Nn + n) * Dn + d] = acc;
    }
}

// ---------------- combine: x = relu(BN1(c1) + h2 bcast); fused BN1 prep + submean ----------------
__global__ void combine_fused(const float* __restrict__ c1, const float* __restrict__ acc,
                              const float* __restrict__ gamma, const float* __restrict__ beta,
                              const float* __restrict__ h2, float* __restrict__ x,
                              float* __restrict__ sub)
{
    int b = blockIdx.x;          // g*Sn + s
    int g = b >> 5;
    int d = threadIdx.x;         // 128
    float mu = acc[d] * (1.f / Tn);
    float var = acc[Dn + d] * (1.f / Tn) - mu * mu;
    const float sc = gamma[d] * rsqrtf(var + EPSn);
    const float sh = beta[d] - mu * sc;
    const float* c1p = c1 + (size_t)b * Nn * Dn;
    const float* h2p = h2 + (size_t)g * Nn * Dn;
    float* xp = x + (size_t)b * Nn * Dn;
    float s = 0.f;
#pragma unroll 4
    for (int n = 0; n < Nn; n++) {
        float v = fmaxf(sc * c1p[n * Dn + d] + sh + h2p[n * Dn + d], 0.f);
        xp[n * Dn + d] = v;
        s += v;
    }
    sub[(size_t)b * Dn + d] = s * (1.f / Nn);
}

// ---------------- head: pool(sub) -> MLP -> logits, + heatmap copy ----------------
__global__ __launch_bounds__(256)
void head_kernel(const float* __restrict__ sub, const float* __restrict__ Wf1,
                 const float* __restrict__ bf1, const float* __restrict__ Wf2,
                 const float* __restrict__ bf2, const float* __restrict__ attn,
                 float* __restrict__ out)
{
    int g = blockIdx.x;
    int tid = threadIdx.x;  // 256
    __shared__ float hv[Dn];
    __shared__ float hid[2 * Dn];
    if (tid < Dn) {
        float s = 0.f;
#pragma unroll 8
        for (int i = 0; i < Sn; i++) s += sub[(size_t)(g * Sn + i) * Dn + tid];
        hv[tid] = s * (1.f / Sn);
    }
    __syncthreads();
    float a = bf1[tid];
#pragma unroll 8
    for (int k2 = 0; k2 < Dn; k2++) a += hv[k2] * Wf1[(size_t)k2 * 2 * Dn + tid];
    hid[tid] = fmaxf(a, 0.f);
    __syncthreads();
    if (tid < NTASK) {
        float o = bf2[tid];
        for (int k2 = 0; k2 < 2 * Dn; k2++) o += hid[k2] * Wf2[(size_t)k2 * NTASK + tid];
        out[(size_t)g * NTASK + tid] = o;
    }
    if (g == Gn - 1) {
        for (int i = tid; i < Sn * Sn; i += 256)
            out[Gn * NTASK + i] = attn[(size_t)(Gn - 1) * Sn * Sn + i];
    }
}

// ---------------- host orchestration ----------------
extern "C" void kernel_launch(void* const* d_in, const int* in_sizes, int n_in,
                              void* d_out, int out_size)
{
    const float* x_in = (const float*)d_in[0];
    const int*   ei   = (const int*)d_in[1];
    const int*   oei  = (const int*)d_in[2];
    const float* Wr1 = (const float*)d_in[3];
    const float* Wn1 = (const float*)d_in[4];
    const float* b1  = (const float*)d_in[5];
    const float* g1  = (const float*)d_in[6];
    const float* be1 = (const float*)d_in[7];
    const float* Wr2 = (const float*)d_in[8];
    const float* Wn2 = (const float*)d_in[9];
    const float* b2  = (const float*)d_in[10];
    const float* g2  = (const float*)d_in[11];
    const float* be2 = (const float*)d_in[12];
    const float* Wq  = (const float*)d_in[13];
    const float* bq  = (const float*)d_in[14];
    const float* Wk  = (const float*)d_in[15];
    const float* bk  = (const float*)d_in[16];
    const float* Wf1 = (const float*)d_in[17];
    const float* bf1 = (const float*)d_in[18];
    const float* Wf2 = (const float*)d_in[19];
    const float* bf2 = (const float*)d_in[20];
    float* out = (float*)d_out;

    float *px, *pagg1, *pc1, *psub, *pq, *pk, *pattn, *pxatt, *pagg2, *pc2, *ph2, *pacc;
    int *pdegs, *poffs, *pcurs, *psrcs;
    cudaGetSymbolAddress((void**)&px,    g_x);
    cudaGetSymbolAddress((void**)&pagg1, g_agg1);
    cudaGetSymbolAddress((void**)&pc1,   g_c1);
    cudaGetSymbolAddress((void**)&psub,  g_sub);
    cudaGetSymbolAddress((void**)&pq,    g_q);
    cudaGetSymbolAddress((void**)&pk,    g_k);
    cudaGetSymbolAddress((void**)&pattn, g_attn);
    cudaGetSymbolAddress((void**)&pxatt, g_xatt);
    cudaGetSymbolAddress((void**)&pagg2, g_agg2);
    cudaGetSymbolAddress((void**)&pc2,   g_c2);
    cudaGetSymbolAddress((void**)&ph2,   g_h2);
    cudaGetSymbolAddress((void**)&pacc,  g_acc);
    cudaGetSymbolAddress((void**)&pdegs, g_degs);
    cudaGetSymbolAddress((void**)&poffs, g_offs);
    cudaGetSymbolAddress((void**)&pcurs, g_curs);
    cudaGetSymbolAddress((void**)&psrcs, g_srcs_all);

    // ---- build CSR for both graphs (layer-invariant): 4 launches ----
    cudaMemsetAsync(pdegs, 0, sizeof(int) * (Tn + TOn), 0);
    hist_both<<<(En + EOn) / 256, 256>>>(ei + En, oei + EOn, pdegs);
    scan_both<<<2, 1024>>>(pdegs, poffs, pcurs);
    fill_both<<<(En + EOn) / 256, 256>>>(ei, oei, pcurs, psrcs);

    const int* poffBig = poffs;
    const int* poffSm  = poffs + Tn + 1;
    const int* psrcBig = psrcs;
    const int* psrcSm  = psrcs + En;

    const float* xcur = x_in;

    for (int i = 0; i < Ln; i++) {
        const size_t wOff = (size_t)i * Dn * Dn;
        const size_t vOff = (size_t)i * Dn;

        // subgraph-level GraphConv (+ fused BN stats; gather1 zeroes the stat acc)
        gather_kernel<<<(Tn * 32) / 256, 256>>>(xcur, poffBig, psrcBig, pagg1, Tn, pacc);
        conv_gemm_tf32<<<Tn / 128, 256>>>(xcur, pagg1, Wr1 + wOff, Wn1 + wOff,
                                          b1 + vOff, pc1, pacc,
                                          nullptr, nullptr, nullptr);

        // attention branch (sub produced by previous combine, except layer 0)
        if (i == 0) submean_kernel<<<Gn * Sn, 128>>>(xcur, psub);
        conv_gemm_tf32<<<dim3((Gn * Sn) / 128, 2), 256>>>(
            psub, nullptr, Wq + wOff, nullptr, bq + vOff, pq, nullptr,
            Wk + wOff, bk + vOff, pk);
        attn_xatten_kernel<<<Gn, 256>>>(pq, pk, xcur, pattn, pxatt);

        // original-graph GraphConv (+ fused BN stats)
        gather_kernel<<<(TOn * 32) / 256, 256>>>(pxatt, poffSm, psrcSm, pagg2, TOn, nullptr);
        conv_gemm_tf32<<<TOn / 128, 256>>>(pxatt, pagg2, Wr2 + wOff, Wn2 + wOff,
                                           b2 + vOff, pc2, pacc + 256,
                                           nullptr, nullptr, nullptr);
        bn_apply2<<<(TOn * Dn) / 256, 256>>>(pc2, pacc + 256, g2 + vOff, be2 + vOff, ph2);

        // x = relu(BN1(c1) + h2 broadcast); BN1 prep + next-layer submean fused
        combine_fused<<<Gn * Sn, 128>>>(pc1, pacc, g1 + vOff, be1 + vOff, ph2, px, psub);
        xcur = px;
    }

    head_kernel<<<Gn, 256>>>(psub, Wf1, bf1, Wf2, bf2, pattn, out);
}

// round 9
// speedup vs baseline: 1.1146x; 1.1146x over previous
#include <cuda_runtime.h>
#include <cuda_fp16.h>
#include <cstdint>

#define Gn 128
#define Sn 32
#define Nn 32
#define Dn 128
#define Ln 3
#define Hn 4
#define HDn 32
#define Tn (Gn*Sn*Nn)        // 131072
#define TOn (Gn*Nn)          // 4096
#define En 1048576
#define EOn 16384
#define NTASK 10
#define EPSn 1e-5f

// ---------------- device scratch (allocation-free) ----------------
__device__ float g_x[Tn*Dn];
__device__ __half g_xh[Tn*Dn];      // fp16 mirror of x for gather/xatten reads
__device__ float g_agg1[Tn*Dn];
__device__ float g_c1[Tn*Dn];
__device__ float g_sub[Gn*Sn*Dn];
__device__ float g_q[Gn*Sn*Dn];
__device__ float g_k[Gn*Sn*Dn];
__device__ float g_attn[Gn*Sn*Sn];
__device__ float g_xatt[TOn*Dn];
__device__ float g_agg2[TOn*Dn];
__device__ float g_c2[TOn*Dn];
__device__ float g_h2[TOn*Dn];
__device__ float g_acc[512];
// combined CSR scratch (big graph at base 0 / En, original graph at base Tn / En)
__device__ int g_degs[Tn + TOn];
__device__ int g_offs[Tn + 1 + TOn + 1];
__device__ int g_curs[Tn + TOn];
__device__ int g_srcs_all[En + EOn];

// ---------------- layer-0 x -> half mirror, also zeroes deg counters ----------------
__global__ void x2half_kernel(const float* __restrict__ x, __half* __restrict__ xh,
                              int* __restrict__ degs)
{
    int idx = blockIdx.x * blockDim.x + threadIdx.x;
    if (idx < Tn + TOn) degs[idx] = 0;
    if (idx < Tn * Dn / 2) {
        float2 v = __ldg(((const float2*)x) + idx);
        ((__half2*)xh)[idx] = __floats2half2_rn(v.x, v.y);
    }
}

// ---------------- CSR build (combined for both graphs) ----------------
__global__ void hist_both(const int* __restrict__ dstBig, const int* __restrict__ dstSmall,
                          int* __restrict__ degs)
{
    int e = blockIdx.x * blockDim.x + threadIdx.x;
    if (e < En) {
        atomicAdd(&degs[__ldg(&dstBig[e])], 1);
    } else if (e < En + EOn) {
        atomicAdd(&degs[Tn + __ldg(&dstSmall[e - En])], 1);
    }
}

// 2 blocks: block 0 scans big graph (Tn), block 1 scans small graph (TOn)
__global__ __launch_bounds__(1024)
void scan_both(const int* __restrict__ degs, int* __restrict__ offs, int* __restrict__ curs)
{
    __shared__ int part[1024];
    const int t = threadIdx.x;
    const int n = (blockIdx.x == 0) ? Tn : TOn;
    const int dbase = (blockIdx.x == 0) ? 0 : Tn;
    const int obase = (blockIdx.x == 0) ? 0 : (Tn + 1);
    const int chunk = n / 1024;
    const int base = t * chunk;
    int s = 0;
    for (int i = 0; i < chunk; i++) s += degs[dbase + base + i];
    part[t] = s;
    __syncthreads();
    for (int d = 1; d < 1024; d <<= 1) {
        int v = (t >= d) ? part[t - d] : 0;
        __syncthreads();
        part[t] += v;
        __syncthreads();
    }
    int run = (t > 0) ? part[t - 1] : 0;
    for (int i = 0; i < chunk; i++) {
        offs[obase + base + i] = run;
        curs[dbase + base + i] = run;
        run += degs[dbase + base + i];
    }
    if (t == 1023) offs[obase + n] = run;
}

__global__ void fill_both(const int* __restrict__ ei, const int* __restrict__ oei,
                          int* __restrict__ curs, int* __restrict__ srcs_all)
{
    int e = blockIdx.x * blockDim.x + threadIdx.x;
    if (e < En) {
        int d = __ldg(&ei[En + e]);              // dst
        int pos = atomicAdd(&curs[d], 1);
        srcs_all[pos] = __ldg(&ei[e]);           // src
    } else if (e < En + EOn) {
        int eo = e - En;
        int d = __ldg(&oei[EOn + eo]);
        int pos = atomicAdd(&curs[Tn + d], 1);
        srcs_all[En + pos] = __ldg(&oei[eo]);
    }
}

// ---------------- CSR gather (half input): warp per node, 4 halfs/lane ----------------
// Block 0 zeroes accZero[0:512] (BN1+BN2 stats accumulator) if non-null.
__global__ void gather_half(const __half* __restrict__ xh, const int* __restrict__ off,
                            const int* __restrict__ srcs, float* __restrict__ agg,
                            float* __restrict__ accZero)
{
    if (accZero && blockIdx.x == 0) {
        accZero[threadIdx.x] = 0.f;
        accZero[threadIdx.x + 256] = 0.f;
    }
    int node = (blockIdx.x * blockDim.x + threadIdx.x) >> 5;
    int lane = threadIdx.x & 31;
    if (node >= Tn) return;
    int e0 = __ldg(&off[node]);
    int e1 = __ldg(&off[node + 1]);
    float4 a0 = make_float4(0.f, 0.f, 0.f, 0.f);
    float4 a1 = make_float4(0.f, 0.f, 0.f, 0.f);
    int e = e0;
    for (; e + 1 < e1; e += 2) {
        int sA = __ldg(&srcs[e]);
        int sB = __ldg(&srcs[e + 1]);
        uint2 ua = __ldg(((const uint2*)(xh + (size_t)sA * Dn)) + lane);
        uint2 ub = __ldg(((const uint2*)(xh + (size_t)sB * Dn)) + lane);
        float2 fa0 = __half22float2(*(__half2*)&ua.x);
        float2 fa1 = __half22float2(*(__half2*)&ua.y);
        float2 fb0 = __half22float2(*(__half2*)&ub.x);
        float2 fb1 = __half22float2(*(__half2*)&ub.y);
        a0.x += fa0.x; a0.y += fa0.y; a0.z += fa1.x; a0.w += fa1.y;
        a1.x += fb0.x; a1.y += fb0.y; a1.z += fb1.x; a1.w += fb1.y;
    }
    if (e < e1) {
        int sA = __ldg(&srcs[e]);
        uint2 ua = __ldg(((const uint2*)(xh + (size_t)sA * Dn)) + lane);
        float2 fa0 = __half22float2(*(__half2*)&ua.x);
        float2 fa1 = __half22float2(*(__half2*)&ua.y);
        a0.x += fa0.x; a0.y += fa0.y; a0.z += fa1.x; a0.w += fa1.y;
    }
    a0.x += a1.x; a0.y += a1.y; a0.z += a1.z; a0.w += a1.w;
    ((float4*)(agg + (size_t)node * Dn))[lane] = a0;
}

// ---------------- CSR gather (fp32, small graph) ----------------
__global__ void gather_f32(const float* __restrict__ x, const int* __restrict__ off,
                           const int* __restrict__ srcs, float* __restrict__ agg, int nNodes)
{
    int node = (blockIdx.x * blockDim.x + threadIdx.x) >> 5;
    int lane = threadIdx.x & 31;
    if (node >= nNodes) return;
    int e0 = __ldg(&off[node]);
    int e1 = __ldg(&off[node + 1]);
    float4 a0 = make_float4(0.f, 0.f, 0.f, 0.f);
    for (int e = e0; e < e1; e++) {
        int sA = __ldg(&srcs[e]);
        float4 va = __ldg(((const float4*)(x + (size_t)sA * Dn)) + lane);
        a0.x += va.x; a0.y += va.y; a0.z += va.z; a0.w += va.w;
    }
    ((float4*)(agg + (size_t)node * Dn))[lane] = a0;
}

// ---------------- cp.async helpers ----------------
__device__ __forceinline__ void cpasync16(void* dst, const void* src)
{
    uint32_t d = (uint32_t)__cvta_generic_to_shared(dst);
    asm volatile("cp.async.cg.shared.global [%0], [%1], 16;" :: "r"(d), "l"(src));
}
__device__ __forceinline__ void cpasync_commit() { asm volatile("cp.async.commit_group;"); }
template<int N> __device__ __forceinline__ void cpasync_wait() { asm volatile("cp.async.wait_group %0;" :: "n"(N)); }

// ---------------- tf32 tensor-core GEMM: C = A1@W1 (+ A2@W2) + bias ----------------
// 128x128 tile, BK=16, 2-stage static-smem double buffer, 256 threads (8 warps 2x4),
// warp tile 64x32 via m16n8k8. Raw fp32 bits fed as tf32 (truncation).
// blockIdx.y==1 selects alternate (W1b, biasb, Cb) operand set (Q/K fusion).
#define ASTR 20
#define BSTR 136
#define A_ST (128 * ASTR)
#define B_ST (16 * BSTR)
__global__ __launch_bounds__(256)
void conv_gemm_tf32(const float* __restrict__ A1, const float* __restrict__ A2,
                    const float* __restrict__ W1in, const float* __restrict__ W2,
                    const float* __restrict__ biasin, float* __restrict__ Cin,
                    float* __restrict__ statAcc,
                    const float* __restrict__ W1b, const float* __restrict__ biasb,
                    float* __restrict__ Cb)
{
    __shared__ float As[2 * A_ST];
    __shared__ float Bs[2 * B_ST];

    const float* W1 = (blockIdx.y == 0) ? W1in : W1b;
    const float* bias = (blockIdx.y == 0) ? biasin : biasb;
    float* C = (blockIdx.y == 0) ? Cin : Cb;

    const int tid = threadIdx.x;
    const int wid = tid >> 5, lane = tid & 31;
    const int wm = wid >> 2, wn = wid & 3;
    const int group = lane >> 2, tig = lane & 3;
    const int row0 = blockIdx.x * 128;
    const int nst = (A2 != nullptr) ? 16 : 8;

    float acc[4][4][4];
#pragma unroll
    for (int i = 0; i < 4; i++)
#pragma unroll
        for (int j = 0; j < 4; j++)
#pragma unroll
            for (int r = 0; r < 4; r++) acc[i][j][r] = 0.f;

    auto load_stage = [&](int kt) {
        const float* A = (kt >= 8) ? A2 : A1;
        const float* W = (kt >= 8) ? W2 : W1;
        const int kg = (kt & 7) * 16;
        float* as = As + (kt & 1) * A_ST;
        float* bs = Bs + (kt & 1) * B_ST;
#pragma unroll
        for (int p = 0; p < 2; p++) {
            int f = tid + p * 256;
            int row = f >> 2, kq = f & 3;
            cpasync16(as + row * ASTR + kq * 4,
                      A + (size_t)(row0 + row) * Dn + kg + kq * 4);
        }
#pragma unroll
        for (int p = 0; p < 2; p++) {
            int f = tid + p * 256;
            int row = f >> 5, nq = f & 31;
            cpasync16(bs + row * BSTR + nq * 4,
                      W + (size_t)(kg + row) * Dn + nq * 4);
        }
        cpasync_commit();
    };

    load_stage(0);
    for (int s = 0; s < nst; s++) {
        if (s + 1 < nst) { load_stage(s + 1); cpasync_wait<1>(); }
        else             { cpasync_wait<0>(); }
        __syncthreads();

        const uint32_t* sa = (const uint32_t*)(As + (s & 1) * A_ST);
        const uint32_t* sb = (const uint32_t*)(Bs + (s & 1) * B_ST);
#pragma unroll
        for (int ks = 0; ks < 2; ks++) {
            const int k0 = ks * 8;
            uint32_t ua[4][4], ub[4][2];
#pragma unroll
            for (int i = 0; i < 4; i++) {
                int r = wm * 64 + i * 16 + group;
                ua[i][0] = sa[r * ASTR + k0 + tig];
                ua[i][1] = sa[(r + 8) * ASTR + k0 + tig];
                ua[i][2] = sa[r * ASTR + k0 + 4 + tig];
                ua[i][3] = sa[(r + 8) * ASTR + k0 + 4 + tig];
            }
#pragma unroll
            for (int j = 0; j < 4; j++) {
                int n = wn * 32 + j * 8 + group;
                ub[j][0] = sb[(k0 + tig) * BSTR + n];
                ub[j][1] = sb[(k0 + 4 + tig) * BSTR + n];
            }
#pragma unroll
            for (int i = 0; i < 4; i++)
#pragma unroll
                for (int j = 0; j < 4; j++) {
                    asm volatile(
                        "mma.sync.aligned.m16n8k8.row.col.f32.tf32.tf32.f32 "
                        "{%0,%1,%2,%3}, {%4,%5,%6,%7}, {%8,%9}, {%0,%1,%2,%3};"
                        : "+f"(acc[i][j][0]), "+f"(acc[i][j][1]),
                          "+f"(acc[i][j][2]), "+f"(acc[i][j][3])
                        : "r"(ua[i][0]), "r"(ua[i][1]), "r"(ua[i][2]), "r"(ua[i][3]),
                          "r"(ub[j][0]), "r"(ub[j][1]));
                }
        }
        __syncthreads();
    }

#pragma unroll
    for (int j = 0; j < 4; j++) {
        const int n = wn * 32 + j * 8 + tig * 2;
        const float bv0 = __ldg(&bias[n]);
        const float bv1 = __ldg(&bias[n + 1]);
        float s0 = 0.f, s1 = 0.f, q0 = 0.f, q1 = 0.f;
#pragma unroll
        for (int i = 0; i < 4; i++) {
            const int row = row0 + wm * 64 + i * 16 + group;
            float v0 = acc[i][j][0] + bv0;
            float v1 = acc[i][j][1] + bv1;
            float v2 = acc[i][j][2] + bv0;
            float v3 = acc[i][j][3] + bv1;
            *(float2*)(C + (size_t)row * Dn + n)       = make_float2(v0, v1);
            *(float2*)(C + (size_t)(row + 8) * Dn + n) = make_float2(v2, v3);
            s0 += v0 + v2;  q0 += v0 * v0 + v2 * v2;
            s1 += v1 + v3;  q1 += v1 * v1 + v3 * v3;
        }
        if (statAcc) {
#pragma unroll
            for (int off = 4; off <= 16; off <<= 1) {
                s0 += __shfl_down_sync(0xffffffffu, s0, off);
                s1 += __shfl_down_sync(0xffffffffu, s1, off);
                q0 += __shfl_down_sync(0xffffffffu, q0, off);
                q1 += __shfl_down_sync(0xffffffffu, q1, off);
            }
            if (group == 0) {
                atomicAdd(&statAcc[n], s0);
                atomicAdd(&statAcc[Dn + n], q0);
                atomicAdd(&statAcc[n + 1], s1);
                atomicAdd(&statAcc[Dn + n + 1], q1);
            }
        }
    }
}

// ---------------- BN2: prep folded into apply ----------------
__global__ void bn_apply2(const float* __restrict__ c, const float* __restrict__ acc,
                          const float* __restrict__ gamma, const float* __restrict__ beta,
                          float* __restrict__ h)
{
    int idx = blockIdx.x * blockDim.x + threadIdx.x;
    if (idx >= TOn * Dn) return;
    int d = idx & (Dn - 1);
    float mu = acc[d] * (1.f / TOn);
    float var = acc[Dn + d] * (1.f / TOn) - mu * mu;
    float sc = gamma[d] * rsqrtf(var + EPSn);
    float sh = beta[d] - mu * sc;
    h[idx] = sc * c[idx] + sh;
}

// ---------------- sub = mean over N (layer 0 only) ----------------
__global__ void submean_kernel(const float* __restrict__ x, float* __restrict__ sub)
{
    int b = blockIdx.x;
    int d = threadIdx.x;
    const float* xp = x + (size_t)b * Nn * Dn;
    float s = 0.f;
#pragma unroll 8
    for (int n = 0; n < Nn; n++) s += xp[n * Dn + d];
    sub[(size_t)b * Dn + d] = s * (1.f / Nn);
}

// ---------------- attention: per-graph 32x32, head-averaged softmax ----------------
__global__ void attn_kernel(const float* __restrict__ q, const float* __restrict__ k,
                            float* __restrict__ attn)
{
    int g = blockIdx.x;
    int tid = threadIdx.x;              // 128
    __shared__ float qs[Dn * 33];       // transposed [c][qi], stride 33
    __shared__ float ks[Sn * Dn];
    __shared__ float at[Sn * Sn];
    const float* qg = q + (size_t)g * Sn * Dn;
    const float* kg = k + (size_t)g * Sn * Dn;
    for (int i = tid; i < Sn * Dn; i += 128) {
        int qi = i >> 7, c = i & 127;
        qs[c * 33 + qi] = qg[i];
        ks[i] = kg[i];
    }
    for (int i = tid; i < Sn * Sn; i += 128) at[i] = 0.f;
    __syncthreads();

    int h = tid >> 5;
    int qi = tid & 31;
    const float scale = 0.17677669529663687f;  // 1/sqrt(32)
    float sc[Sn];
    float mx = -1e30f;
#pragma unroll
    for (int j = 0; j < Sn; j++) {
        float dsum = 0.f;
#pragma unroll
        for (int hd = 0; hd < HDn; hd++)
            dsum += qs[(h * HDn + hd) * 33 + qi] * ks[j * Dn + h * HDn + hd];
        sc[j] = dsum * scale;
        mx = fmaxf(mx, sc[j]);
    }
    float se = 0.f;
#pragma unroll
    for (int j = 0; j < Sn; j++) { sc[j] = expf(sc[j] - mx); se += sc[j]; }
    float inv = 0.25f / se;   // head-mean folded in
#pragma unroll
    for (int j = 0; j < Sn; j++) atomicAdd(&at[qi * Sn + j], sc[j] * inv);
    __syncthreads();
    for (int i = tid; i < Sn * Sn; i += 128) attn[(size_t)g * Sn * Sn + i] = at[i];
}

// ---------------- x_atten[g,n,d] = sum_s attn[g,s,n]*xh[g,s,n,d] (half reads) ----------------
__global__ void xatten_kernel(const __half* __restrict__ xh, const float* __restrict__ attn,
                              float* __restrict__ xatt)
{
    int b = blockIdx.x;                 // g*Nn + n
    int g = b >> 5, n = b & 31;
    int d = threadIdx.x;                // 128
    __shared__ float coef[Sn];
    if (d < Sn) coef[d] = attn[(size_t)g * Sn * Sn + d * Sn + n];
    __syncthreads();
    float acc = 0.f;
#pragma unroll 8
    for (int s = 0; s < Sn; s++)
        acc += coef[s] * __half2float(xh[(size_t)((g * Sn + s) * Nn + n) * Dn + d]);
    xatt[(size_t)b * Dn + d] = acc;
}

// ---------------- combine: x = relu(BN1(c1) + h2 bcast); BN1 prep + submean + half mirror ----------------
__global__ void combine_fused(const float* __restrict__ c1, const float* __restrict__ acc,
                              const float* __restrict__ gamma, const float* __restrict__ beta,
                              const float* __restrict__ h2, float* __restrict__ x,
                              float* __restrict__ sub, __half* __restrict__ xh)
{
    int b = blockIdx.x;          // g*Sn + s
    int g = b >> 5;
    int d = threadIdx.x;         // 128
    float mu = acc[d] * (1.f / Tn);
    float var = acc[Dn + d] * (1.f / Tn) - mu * mu;
    const float sc = gamma[d] * rsqrtf(var + EPSn);
    const float sh = beta[d] - mu * sc;
    const float* c1p = c1 + (size_t)b * Nn * Dn;
    const float* h2p = h2 + (size_t)g * Nn * Dn;
    float* xp = x + (size_t)b * Nn * Dn;
    __half* xhp = xh ? (xh + (size_t)b * Nn * Dn) : nullptr;
    float s = 0.f;
#pragma unroll 4
    for (int n = 0; n < Nn; n++) {
        float v = fmaxf(sc * c1p[n * Dn + d] + sh + h2p[n * Dn + d], 0.f);
        xp[n * Dn + d] = v;
        if (xhp) xhp[n * Dn + d] = __float2half_rn(v);
        s += v;
    }
    sub[(size_t)b * Dn + d] = s * (1.f / Nn);
}

// ---------------- head: pool(sub) -> MLP -> logits, + heatmap copy ----------------
__global__ __launch_bounds__(256)
void head_kernel(const float* __restrict__ sub, const float* __restrict__ Wf1,
                 const float* __restrict__ bf1, const float* __restrict__ Wf2,
                 const float* __restrict__ bf2, const float* __restrict__ attn,
                 float* __restrict__ out)
{
    int g = blockIdx.x;
    int tid = threadIdx.x;  // 256
    __shared__ float hv[Dn];
    __shared__ float hid[2 * Dn];
    if (tid < Dn) {
        float s = 0.f;
#pragma unroll 8
        for (int i = 0; i < Sn; i++) s += sub[(size_t)(g * Sn + i) * Dn + tid];
        hv[tid] = s * (1.f / Sn);
    }
    __syncthreads();
    float a = bf1[tid];
#pragma unroll 8
    for (int k2 = 0; k2 < Dn; k2++) a += hv[k2] * Wf1[(size_t)k2 * 2 * Dn + tid];
    hid[tid] = fmaxf(a, 0.f);
    __syncthreads();
    if (tid < NTASK) {
        float o = bf2[tid];
        for (int k2 = 0; k2 < 2 * Dn; k2++) o += hid[k2] * Wf2[(size_t)k2 * NTASK + tid];
        out[(size_t)g * NTASK + tid] = o;
    }
    if (g == Gn - 1) {
        for (int i = tid; i < Sn * Sn; i += 256)
            out[Gn * NTASK + i] = attn[(size_t)(Gn - 1) * Sn * Sn + i];
    }
}

// ---------------- host orchestration ----------------
extern "C" void kernel_launch(void* const* d_in, const int* in_sizes, int n_in,
                              void* d_out, int out_size)
{
    const float* x_in = (const float*)d_in[0];
    const int*   ei   = (const int*)d_in[1];
    const int*   oei  = (const int*)d_in[2];
    const float* Wr1 = (const float*)d_in[3];
    const float* Wn1 = (const float*)d_in[4];
    const float* b1  = (const float*)d_in[5];
    const float* g1  = (const float*)d_in[6];
    const float* be1 = (const float*)d_in[7];
    const float* Wr2 = (const float*)d_in[8];
    const float* Wn2 = (const float*)d_in[9];
    const float* b2  = (const float*)d_in[10];
    const float* g2  = (const float*)d_in[11];
    const float* be2 = (const float*)d_in[12];
    const float* Wq  = (const float*)d_in[13];
    const float* bq  = (const float*)d_in[14];
    const float* Wk  = (const float*)d_in[15];
    const float* bk  = (const float*)d_in[16];
    const float* Wf1 = (const float*)d_in[17];
    const float* bf1 = (const float*)d_in[18];
    const float* Wf2 = (const float*)d_in[19];
    const float* bf2 = (const float*)d_in[20];
    float* out = (float*)d_out;

    float *px, *pagg1, *pc1, *psub, *pq, *pk, *pattn, *pxatt, *pagg2, *pc2, *ph2, *pacc;
    __half* pxh;
    int *pdegs, *poffs, *pcurs, *psrcs;
    cudaGetSymbolAddress((void**)&px,    g_x);
    cudaGetSymbolAddress((void**)&pxh,   g_xh);
    cudaGetSymbolAddress((void**)&pagg1, g_agg1);
    cudaGetSymbolAddress((void**)&pc1,   g_c1);
    cudaGetSymbolAddress((void**)&psub,  g_sub);
    cudaGetSymbolAddress((void**)&pq,    g_q);
    cudaGetSymbolAddress((void**)&pk,    g_k);
    cudaGetSymbolAddress((void**)&pattn, g_attn);
    cudaGetSymbolAddress((void**)&pxatt, g_xatt);
    cudaGetSymbolAddress((void**)&pagg2, g_agg2);
    cudaGetSymbolAddress((void**)&pc2,   g_c2);
    cudaGetSymbolAddress((void**)&ph2,   g_h2);
    cudaGetSymbolAddress((void**)&pacc,  g_acc);
    cudaGetSymbolAddress((void**)&pdegs, g_degs);
    cudaGetSymbolAddress((void**)&poffs, g_offs);
    cudaGetSymbolAddress((void**)&pcurs, g_curs);
    cudaGetSymbolAddress((void**)&psrcs, g_srcs_all);

    // ---- layer-0 half mirror + deg zeroing, then CSR build (4 launches total) ----
    x2half_kernel<<<(Tn * Dn / 2) / 256, 256>>>(x_in, pxh, pdegs);
    hist_both<<<(En + EOn) / 256, 256>>>(ei + En, oei + EOn, pdegs);
    scan_both<<<2, 1024>>>(pdegs, poffs, pcurs);
    fill_both<<<(En + EOn) / 256, 256>>>(ei, oei, pcurs, psrcs);

    const int* poffBig = poffs;
    const int* poffSm  = poffs + Tn + 1;
    const int* psrcBig = psrcs;
    const int* psrcSm  = psrcs + En;

    const float* xcur = x_in;

    for (int i = 0; i < Ln; i++) {
        const size_t wOff = (size_t)i * Dn * Dn;
        const size_t vOff = (size_t)i * Dn;

        // subgraph-level GraphConv (+ fused BN stats; gather zeroes the stat acc)
        gather_half<<<(Tn * 32) / 256, 256>>>(pxh, poffBig, psrcBig, pagg1, pacc);
        conv_gemm_tf32<<<Tn / 128, 256>>>(xcur, pagg1, Wr1 + wOff, Wn1 + wOff,
                                          b1 + vOff, pc1, pacc,
                                          nullptr, nullptr, nullptr);

        // attention branch (sub produced by previous combine, except layer 0)
        if (i == 0) submean_kernel<<<Gn * Sn, 128>>>(xcur, psub);
        conv_gemm_tf32<<<dim3((Gn * Sn) / 128, 2), 256>>>(
            psub, nullptr, Wq + wOff, nullptr, bq + vOff, pq, nullptr,
            Wk + wOff, bk + vOff, pk);
        attn_kernel<<<Gn, 128>>>(pq, pk, pattn);
        xatten_kernel<<<Gn * Nn, 128>>>(pxh, pattn, pxatt);

        // original-graph GraphConv (+ fused BN stats)
        gather_f32<<<(TOn * 32) / 256, 256>>>(pxatt, poffSm, psrcSm, pagg2, TOn);
        conv_gemm_tf32<<<TOn / 128, 256>>>(pxatt, pagg2, Wr2 + wOff, Wn2 + wOff,
                                           b2 + vOff, pc2, pacc + 256,
                                           nullptr, nullptr, nullptr);
        bn_apply2<<<(TOn * Dn) / 256, 256>>>(pc2, pacc + 256, g2 + vOff, be2 + vOff, ph2);

        // x = relu(BN1(c1) + h2 broadcast); BN1 prep + submean + half mirror fused
        combine_fused<<<Gn * Sn, 128>>>(pc1, pacc, g1 + vOff, be1 + vOff, ph2, px, psub,
                                        (i < Ln - 1) ? pxh : nullptr);
        xcur = px;
    }

    head_kernel<<<Gn, 256>>>(psub, Wf1, bf1, Wf2, bf2, pattn, out);
}

// round 11
// speedup vs baseline: 1.1664x; 1.0465x over previous
#include <cuda_runtime.h>
#include <cuda_fp16.h>
#include <cstdint>

#define Gn 128
#define Sn 32
#define Nn 32
#define Dn 128
#define Ln 3
#define Hn 4
#define HDn 32
#define Tn (Gn*Sn*Nn)        // 131072
#define TOn (Gn*Nn)          // 4096
#define En 1048576
#define EOn 16384
#define NTASK 10
#define EPSn 1e-5f

// ---------------- device scratch (allocation-free) ----------------
__device__ float  g_x[Tn*Dn];
__device__ __half g_xh[Tn*Dn];       // fp16 mirror of x
__device__ __half g_agg1h[Tn*Dn];    // fp16 aggregate (big graph)
__device__ float  g_c1[Tn*Dn];
__device__ float  g_sub[Gn*Sn*Dn];
__device__ __half g_subh[Gn*Sn*Dn];
__device__ float  g_q[Gn*Sn*Dn];
__device__ float  g_k[Gn*Sn*Dn];
__device__ float  g_attn[Gn*Sn*Sn];
__device__ __half g_xatth[TOn*Dn];
__device__ __half g_agg2h[TOn*Dn];
__device__ float  g_c2[TOn*Dn];
__device__ float  g_h2[TOn*Dn];
__device__ float  g_acc[512];
__device__ __half g_wh[6 * Ln * Dn * Dn];   // transposed half weights [which][l][n][k]
// combined CSR scratch
__device__ int g_degs[Tn + TOn];
__device__ int g_offs[Tn + 1 + TOn + 1];
__device__ int g_curs[Tn + TOn];
__device__ int g_srcs_all[En + EOn];

// ---------------- weight convert + transpose: wh[w][l][n][k] = W[w][l][k][n] ----------------
__global__ void wconv_kernel(const float* __restrict__ Wr1, const float* __restrict__ Wn1,
                             const float* __restrict__ Wr2, const float* __restrict__ Wn2,
                             const float* __restrict__ Wq,  const float* __restrict__ Wk,
                             __half* __restrict__ wh)
{
    int idx = blockIdx.x * blockDim.x + threadIdx.x;      // 0 .. Ln*Dn*Dn-1
    int which = blockIdx.y;
    const float* src = (which == 0) ? Wr1 : (which == 1) ? Wn1 : (which == 2) ? Wr2
                     : (which == 3) ? Wn2 : (which == 4) ? Wq : Wk;
    int l = idx / (Dn * Dn), rem = idx % (Dn * Dn);
    int k = rem / Dn, n = rem % Dn;
    wh[((size_t)which * Ln + l) * Dn * Dn + n * Dn + k] = __float2half_rn(src[idx]);
}

// ---------------- layer-0 x -> half mirror, also zeroes deg counters ----------------
__global__ void x2half_kernel(const float* __restrict__ x, __half* __restrict__ xh,
                              int* __restrict__ degs)
{
    int idx = blockIdx.x * blockDim.x + threadIdx.x;
    if (idx < Tn + TOn) degs[idx] = 0;
    if (idx < Tn * Dn / 2) {
        float2 v = __ldg(((const float2*)x) + idx);
        ((__half2*)xh)[idx] = __floats2half2_rn(v.x, v.y);
    }
}

// ---------------- CSR build ----------------
__global__ void hist_both(const int* __restrict__ dstBig, const int* __restrict__ dstSmall,
                          int* __restrict__ degs)
{
    int e = blockIdx.x * blockDim.x + threadIdx.x;
    if (e < En) {
        atomicAdd(&degs[__ldg(&dstBig[e])], 1);
    } else if (e < En + EOn) {
        atomicAdd(&degs[Tn + __ldg(&dstSmall[e - En])], 1);
    }
}

__global__ __launch_bounds__(1024)
void scan_both(const int* __restrict__ degs, int* __restrict__ offs, int* __restrict__ curs)
{
    __shared__ int part[1024];
    const int t = threadIdx.x;
    const int n = (blockIdx.x == 0) ? Tn : TOn;
    const int dbase = (blockIdx.x == 0) ? 0 : Tn;
    const int obase = (blockIdx.x == 0) ? 0 : (Tn + 1);
    const int chunk = n / 1024;
    const int base = t * chunk;
    int s = 0;
    for (int i = 0; i < chunk; i++) s += degs[dbase + base + i];
    part[t] = s;
    __syncthreads();
    for (int d = 1; d < 1024; d <<= 1) {
        int v = (t >= d) ? part[t - d] : 0;
        __syncthreads();
        part[t] += v;
        __syncthreads();
    }
    int run = (t > 0) ? part[t - 1] : 0;
    for (int i = 0; i < chunk; i++) {
        offs[obase + base + i] = run;
        curs[dbase + base + i] = run;
        run += degs[dbase + base + i];
    }
    if (t == 1023) offs[obase + n] = run;
}

__global__ void fill_both(const int* __restrict__ ei, const int* __restrict__ oei,
                          int* __restrict__ curs, int* __restrict__ srcs_all)
{
    int e = blockIdx.x * blockDim.x + threadIdx.x;
    if (e < En) {
        int d = __ldg(&ei[En + e]);
        int pos = atomicAdd(&curs[d], 1);
        srcs_all[pos] = __ldg(&ei[e]);
    } else if (e < En + EOn) {
        int eo = e - En;
        int d = __ldg(&oei[EOn + eo]);
        int pos = atomicAdd(&curs[Tn + d], 1);
        srcs_all[En + pos] = __ldg(&oei[eo]);
    }
}

// ---------------- CSR gather: half in, fp32 accum, half out ----------------
// Block 0 zeroes accZero[0:512] if non-null.
__global__ void gather_half(const __half* __restrict__ xh, const int* __restrict__ off,
                            const int* __restrict__ srcs, __half* __restrict__ aggh,
                            int nNodes, float* __restrict__ accZero)
{
    if (accZero && blockIdx.x == 0) {
        accZero[threadIdx.x] = 0.f;
        accZero[threadIdx.x + 256] = 0.f;
    }
    int node = (blockIdx.x * blockDim.x + threadIdx.x) >> 5;
    int lane = threadIdx.x & 31;
    if (node >= nNodes) return;
    int e0 = __ldg(&off[node]);
    int e1 = __ldg(&off[node + 1]);
    float4 a0 = make_float4(0.f, 0.f, 0.f, 0.f);
    float4 a1 = make_float4(0.f, 0.f, 0.f, 0.f);
    int e = e0;
    for (; e + 1 < e1; e += 2) {
        int sA = __ldg(&srcs[e]);
        int sB = __ldg(&srcs[e + 1]);
        uint2 ua = __ldg(((const uint2*)(xh + (size_t)sA * Dn)) + lane);
        uint2 ub = __ldg(((const uint2*)(xh + (size_t)sB * Dn)) + lane);
        float2 fa0 = __half22float2(*(__half2*)&ua.x);
        float2 fa1 = __half22float2(*(__half2*)&ua.y);
        float2 fb0 = __half22float2(*(__half2*)&ub.x);
        float2 fb1 = __half22float2(*(__half2*)&ub.y);
        a0.x += fa0.x; a0.y += fa0.y; a0.z += fa1.x; a0.w += fa1.y;
        a1.x += fb0.x; a1.y += fb0.y; a1.z += fb1.x; a1.w += fb1.y;
    }
    if (e < e1) {
        int sA = __ldg(&srcs[e]);
        uint2 ua = __ldg(((const uint2*)(xh + (size_t)sA * Dn)) + lane);
        float2 fa0 = __half22float2(*(__half2*)&ua.x);
        float2 fa1 = __half22float2(*(__half2*)&ua.y);
        a0.x += fa0.x; a0.y += fa0.y; a0.z += fa1.x; a0.w += fa1.y;
    }
    a0.x += a1.x; a0.y += a1.y; a0.z += a1.z; a0.w += a1.w;
    uint2 o;
    *(__half2*)&o.x = __floats2half2_rn(a0.x, a0.y);
    *(__half2*)&o.y = __floats2half2_rn(a0.z, a0.w);
    ((uint2*)(aggh + (size_t)node * Dn))[lane] = o;
}

// ---------------- cp.async helpers ----------------
__device__ __forceinline__ void cpasync16(void* dst, const void* src)
{
    uint32_t d = (uint32_t)__cvta_generic_to_shared(dst);
    asm volatile("cp.async.cg.shared.global [%0], [%1], 16;" :: "r"(d), "l"(src));
}
__device__ __forceinline__ void cpasync_commit() { asm volatile("cp.async.commit_group;"); }
template<int N> __device__ __forceinline__ void cpasync_wait() { asm volatile("cp.async.wait_group %0;" :: "n"(N)); }

// ---------------- fp16 tensor-core GEMM: C = A1@W1 (+ A2@W2) + bias ----------------
// A row-major half [m][128]; W transposed half [n][128]. 128x128 tile, BK=16,
// 2-stage double buffer, 256 threads (8 warps 2x4), warp tile 64x32 via m16n8k16.
// fp32 accumulate + epilogue. blockIdx.y==1 selects (W1b, biasb, Cb).
#define ASTRH 24                 // halves per row (16 + 8 pad) -> 12 uints, conflict-free
#define A_STH (128 * ASTRH)
#define B_STH (128 * ASTRH)
__global__ __launch_bounds__(256)
void conv_gemm_f16(const __half* __restrict__ A1, const __half* __restrict__ A2,
                   const __half* __restrict__ W1in, const __half* __restrict__ W2,
                   const float* __restrict__ biasin, float* __restrict__ Cin,
                   float* __restrict__ statAcc,
                   const __half* __restrict__ W1b, const float* __restrict__ biasb,
                   float* __restrict__ Cb)
{
    __shared__ __half As[2 * A_STH];
    __shared__ __half Bs[2 * B_STH];

    const __half* W1 = (blockIdx.y == 0) ? W1in : W1b;
    const float* bias = (blockIdx.y == 0) ? biasin : biasb;
    float* C = (blockIdx.y == 0) ? Cin : Cb;

    const int tid = threadIdx.x;
    const int wid = tid >> 5, lane = tid & 31;
    const int wm = wid >> 2, wn = wid & 3;
    const int group = lane >> 2, tig = lane & 3;
    const int row0 = blockIdx.x * 128;
    const int nst = (A2 != nullptr) ? 16 : 8;

    float acc[4][4][4];
#pragma unroll
    for (int i = 0; i < 4; i++)
#pragma unroll
        for (int j = 0; j < 4; j++)
#pragma unroll
            for (int r = 0; r < 4; r++) acc[i][j][r] = 0.f;

    auto load_stage = [&](int kt) {
        const __half* A = (kt >= 8) ? A2 : A1;
        const __half* W = (kt >= 8) ? W2 : W1;
        const int kg = (kt & 7) * 16;
        __half* as = As + (kt & 1) * A_STH;
        __half* bs = Bs + (kt & 1) * B_STH;
        {   // A tile: 128 rows x 16 halves = 256 x 16B
            int row = tid >> 1, koff = (tid & 1) * 8;
            cpasync16(as + row * ASTRH + koff,
                      A + (size_t)(row0 + row) * Dn + kg + koff);
        }
        {   // B tile: 128 n x 16 halves
            int n = tid >> 1, koff = (tid & 1) * 8;
            cpasync16(bs + n * ASTRH + koff,
                      W + (size_t)n * Dn + kg + koff);
        }
        cpasync_commit();
    };

    load_stage(0);
    for (int s = 0; s < nst; s++) {
        if (s + 1 < nst) { load_stage(s + 1); cpasync_wait<1>(); }
        else             { cpasync_wait<0>(); }
        __syncthreads();

        const uint32_t* sa = (const uint32_t*)(As + (s & 1) * A_STH);
        const uint32_t* sb = (const uint32_t*)(Bs + (s & 1) * B_STH);
        uint32_t ua[4][4], ub[4][2];
#pragma unroll
        for (int i = 0; i < 4; i++) {
            int r = wm * 64 + i * 16 + group;
            ua[i][0] = sa[r * 12 + tig];
            ua[i][1] = sa[(r + 8) * 12 + tig];
            ua[i][2] = sa[r * 12 + tig + 4];
            ua[i][3] = sa[(r + 8) * 12 + tig + 4];
        }
#pragma unroll
        for (int j = 0; j < 4; j++) {
            int n = wn * 32 + j * 8 + group;
            ub[j][0] = sb[n * 12 + tig];
            ub[j][1] = sb[n * 12 + tig + 4];
        }
#pragma unroll
        for (int i = 0; i < 4; i++)
#pragma unroll
            for (int j = 0; j < 4; j++) {
                asm volatile(
                    "mma.sync.aligned.m16n8k16.row.col.f32.f16.f16.f32 "
                    "{%0,%1,%2,%3}, {%4,%5,%6,%7}, {%8,%9}, {%0,%1,%2,%3};"
                    : "+f"(acc[i][j][0]), "+f"(acc[i][j][1]),
                      "+f"(acc[i][j][2]), "+f"(acc[i][j][3])
                    : "r"(ua[i][0]), "r"(ua[i][1]), "r"(ua[i][2]), "r"(ua[i][3]),
                      "r"(ub[j][0]), "r"(ub[j][1]));
            }
        __syncthreads();
    }

#pragma unroll
    for (int j = 0; j < 4; j++) {
        const int n = wn * 32 + j * 8 + tig * 2;
        const float bv0 = __ldg(&bias[n]);
        const float bv1 = __ldg(&bias[n + 1]);
        float s0 = 0.f, s1 = 0.f, q0 = 0.f, q1 = 0.f;
#pragma unroll
        for (int i = 0; i < 4; i++) {
            const int row = row0 + wm * 64 + i * 16 + group;
            float v0 = acc[i][j][0] + bv0;
            float v1 = acc[i][j][1] + bv1;
            float v2 = acc[i][j][2] + bv0;
            float v3 = acc[i][j][3] + bv1;
            *(float2*)(C + (size_t)row * Dn + n)       = make_float2(v0, v1);
            *(float2*)(C + (size_t)(row + 8) * Dn + n) = make_float2(v2, v3);
            s0 += v0 + v2;  q0 += v0 * v0 + v2 * v2;
            s1 += v1 + v3;  q1 += v1 * v1 + v3 * v3;
        }
        if (statAcc) {
#pragma unroll
            for (int off = 4; off <= 16; off <<= 1) {
                s0 += __shfl_down_sync(0xffffffffu, s0, off);
                s1 += __shfl_down_sync(0xffffffffu, s1, off);
                q0 += __shfl_down_sync(0xffffffffu, q0, off);
                q1 += __shfl_down_sync(0xffffffffu, q1, off);
            }
            if (group == 0) {
                atomicAdd(&statAcc[n], s0);
                atomicAdd(&statAcc[Dn + n], q0);
                atomicAdd(&statAcc[n + 1], s1);
                atomicAdd(&statAcc[Dn + n + 1], q1);
            }
        }
    }
}

// ---------------- BN2: prep folded into apply ----------------
__global__ void bn_apply2(const float* __restrict__ c, const float* __restrict__ acc,
                          const float* __restrict__ gamma, const float* __restrict__ beta,
                          float* __restrict__ h)
{
    int idx = blockIdx.x * blockDim.x + threadIdx.x;
    if (idx >= TOn * Dn) return;
    int d = idx & (Dn - 1);
    float mu = acc[d] * (1.f / TOn);
    float var = acc[Dn + d] * (1.f / TOn) - mu * mu;
    float sc = gamma[d] * rsqrtf(var + EPSn);
    float sh = beta[d] - mu * sc;
    h[idx] = sc * c[idx] + sh;
}

// ---------------- sub = mean over N (layer 0 only), fp32 + half ----------------
__global__ void submean_kernel(const float* __restrict__ x, float* __restrict__ sub,
                               __half* __restrict__ subh)
{
    int b = blockIdx.x;
    int d = threadIdx.x;
    const float* xp = x + (size_t)b * Nn * Dn;
    float s = 0.f;
#pragma unroll 8
    for (int n = 0; n < Nn; n++) s += xp[n * Dn + d];
    float m = s * (1.f / Nn);
    sub[(size_t)b * Dn + d] = m;
    subh[(size_t)b * Dn + d] = __float2half_rn(m);
}

// ---------------- attention: per-graph 32x32, head-averaged softmax ----------------
__global__ void attn_kernel(const float* __restrict__ q, const float* __restrict__ k,
                            float* __restrict__ attn)
{
    int g = blockIdx.x;
    int tid = threadIdx.x;              // 128
    __shared__ float qs[Dn * 33];
    __shared__ float ks[Sn * Dn];
    __shared__ float at[Sn * Sn];
    const float* qg = q + (size_t)g * Sn * Dn;
    const float* kg = k + (size_t)g * Sn * Dn;
    for (int i = tid; i < Sn * Dn; i += 128) {
        int qi = i >> 7, c = i & 127;
        qs[c * 33 + qi] = qg[i];
        ks[i] = kg[i];
    }
    for (int i = tid; i < Sn * Sn; i += 128) at[i] = 0.f;
    __syncthreads();

    int h = tid >> 5;
    int qi = tid & 31;
    const float scale = 0.17677669529663687f;  // 1/sqrt(32)
    float sc[Sn];
    float mx = -1e30f;
#pragma unroll
    for (int j = 0; j < Sn; j++) {
        float dsum = 0.f;
#pragma unroll
        for (int hd = 0; hd < HDn; hd++)
            dsum += qs[(h * HDn + hd) * 33 + qi] * ks[j * Dn + h * HDn + hd];
        sc[j] = dsum * scale;
        mx = fmaxf(mx, sc[j]);
    }
    float se = 0.f;
#pragma unroll
    for (int j = 0; j < Sn; j++) { sc[j] = expf(sc[j] - mx); se += sc[j]; }
    float inv = 0.25f / se;
#pragma unroll
    for (int j = 0; j < Sn; j++) atomicAdd(&at[qi * Sn + j], sc[j] * inv);
    __syncthreads();
    for (int i = tid; i < Sn * Sn; i += 128) attn[(size_t)g * Sn * Sn + i] = at[i];
}

// ---------------- x_atten[g,n,d] = sum_s attn[g,s,n]*xh[g,s,n,d] -> half ----------------
__global__ void xatten_kernel(const __half* __restrict__ xh, const float* __restrict__ attn,
                              __half* __restrict__ xatth)
{
    int b = blockIdx.x;                 // g*Nn + n
    int g = b >> 5, n = b & 31;
    int d = threadIdx.x;                // 128
    __shared__ float coef[Sn];
    if (d < Sn) coef[d] = attn[(size_t)g * Sn * Sn + d * Sn + n];
    __syncthreads();
    float acc = 0.f;
#pragma unroll 8
    for (int s = 0; s < Sn; s++)
        acc += coef[s] * __half2float(xh[(size_t)((g * Sn + s) * Nn + n) * Dn + d]);
    xatth[(size_t)b * Dn + d] = __float2half_rn(acc);
}

// ---------------- combine: x = relu(BN1(c1)+h2); BN1 prep + submean + half mirrors ----------------
__global__ void combine_fused(const float* __restrict__ c1, const float* __restrict__ acc,
                              const float* __restrict__ gamma, const float* __restrict__ beta,
                              const float* __restrict__ h2, float* __restrict__ x,
                              float* __restrict__ sub, __half* __restrict__ subh,
                              __half* __restrict__ xh)
{
    int b = blockIdx.x;          // g*Sn + s
    int g = b >> 5;
    int d = threadIdx.x;         // 128
    float mu = acc[d] * (1.f / Tn);
    float var = acc[Dn + d] * (1.f / Tn) - mu * mu;
    const float sc = gamma[d] * rsqrtf(var + EPSn);
    const float sh = beta[d] - mu * sc;
    const float* c1p = c1 + (size_t)b * Nn * Dn;
    const float* h2p = h2 + (size_t)g * Nn * Dn;
    float* xp = x + (size_t)b * Nn * Dn;
    __half* xhp = xh ? (xh + (size_t)b * Nn * Dn) : nullptr;
    float s = 0.f;
#pragma unroll 4
    for (int n = 0; n < Nn; n++) {
        float v = fmaxf(sc * c1p[n * Dn + d] + sh + h2p[n * Dn + d], 0.f);
        xp[n * Dn + d] = v;
        if (xhp) xhp[n * Dn + d] = __float2half_rn(v);
        s += v;
    }
    float m = s * (1.f / Nn);
    sub[(size_t)b * Dn + d] = m;
    subh[(size_t)b * Dn + d] = __float2half_rn(m);
}

// ---------------- head: pool(sub) -> MLP -> logits, + heatmap copy ----------------
__global__ __launch_bounds__(256)
void head_kernel(const float* __restrict__ sub, const float* __restrict__ Wf1,
                 const float* __restrict__ bf1, const float* __restrict__ Wf2,
                 const float* __restrict__ bf2, const float* __restrict__ attn,
                 float* __restrict__ out)
{
    int g = blockIdx.x;
    int tid = threadIdx.x;  // 256
    __shared__ float hv[Dn];
    __shared__ float hid[2 * Dn];
    if (tid < Dn) {
        float s = 0.f;
#pragma unroll 8
        for (int i = 0; i < Sn; i++) s += sub[(size_t)(g * Sn + i) * Dn + tid];
        hv[tid] = s * (1.f / Sn);
    }
    __syncthreads();
    float a = bf1[tid];
#pragma unroll 8
    for (int k2 = 0; k2 < Dn; k2++) a += hv[k2] * Wf1[(size_t)k2 * 2 * Dn + tid];
    hid[tid] = fmaxf(a, 0.f);
    __syncthreads();
    if (tid < NTASK) {
        float o = bf2[tid];
        for (int k2 = 0; k2 < 2 * Dn; k2++) o += hid[k2] * Wf2[(size_t)k2 * NTASK + tid];
        out[(size_t)g * NTASK + tid] = o;
    }
    if (g == Gn - 1) {
        for (int i = tid; i < Sn * Sn; i += 256)
            out[Gn * NTASK + i] = attn[(size_t)(Gn - 1) * Sn * Sn + i];
    }
}

// ---------------- host orchestration ----------------
extern "C" void kernel_launch(void* const* d_in, const int* in_sizes, int n_in,
                              void* d_out, int out_size)
{
    const float* x_in = (const float*)d_in[0];
    const int*   ei   = (const int*)d_in[1];
    const int*   oei  = (const int*)d_in[2];
    const float* Wr1 = (const float*)d_in[3];
    const float* Wn1 = (const float*)d_in[4];
    const float* b1  = (const float*)d_in[5];
    const float* g1  = (const float*)d_in[6];
    const float* be1 = (const float*)d_in[7];
    const float* Wr2 = (const float*)d_in[8];
    const float* Wn2 = (const float*)d_in[9];
    const float* b2  = (const float*)d_in[10];
    const float* g2  = (const float*)d_in[11];
    const float* be2 = (const float*)d_in[12];
    const float* Wq  = (const float*)d_in[13];
    const float* bq  = (const float*)d_in[14];
    const float* Wk  = (const float*)d_in[15];
    const float* bk  = (const float*)d_in[16];
    const float* Wf1 = (const float*)d_in[17];
    const float* bf1 = (const float*)d_in[18];
    const float* Wf2 = (const float*)d_in[19];
    const float* bf2 = (const float*)d_in[20];
    float* out = (float*)d_out;

    float *px, *pc1, *psub, *pq, *pk, *pattn, *pc2, *ph2, *pacc;
    __half *pxh, *pagg1h, *psubh, *pxatth, *pagg2h, *pwh;
    int *pdegs, *poffs, *pcurs, *psrcs;
    cudaGetSymbolAddress((void**)&px,     g_x);
    cudaGetSymbolAddress((void**)&pxh,    g_xh);
    cudaGetSymbolAddress((void**)&pagg1h, g_agg1h);
    cudaGetSymbolAddress((void**)&pc1,    g_c1);
    cudaGetSymbolAddress((void**)&psub,   g_sub);
    cudaGetSymbolAddress((void**)&psubh,  g_subh);
    cudaGetSymbolAddress((void**)&pq,     g_q);
    cudaGetSymbolAddress((void**)&pk,     g_k);
    cudaGetSymbolAddress((void**)&pattn,  g_attn);
    cudaGetSymbolAddress((void**)&pxatth, g_xatth);
    cudaGetSymbolAddress((void**)&pagg2h, g_agg2h);
    cudaGetSymbolAddress((void**)&pc2,    g_c2);
    cudaGetSymbolAddress((void**)&ph2,    g_h2);
    cudaGetSymbolAddress((void**)&pacc,   g_acc);
    cudaGetSymbolAddress((void**)&pwh,    g_wh);
    cudaGetSymbolAddress((void**)&pdegs,  g_degs);
    cudaGetSymbolAddress((void**)&poffs,  g_offs);
    cudaGetSymbolAddress((void**)&pcurs,  g_curs);
    cudaGetSymbolAddress((void**)&psrcs,  g_srcs_all);

    // ---- startup: weight convert, half mirror + deg zero, CSR build ----
    wconv_kernel<<<dim3(Ln * Dn * Dn / 256, 6), 256>>>(Wr1, Wn1, Wr2, Wn2, Wq, Wk, pwh);
    x2half_kernel<<<(Tn * Dn / 2) / 256, 256>>>(x_in, pxh, pdegs);
    hist_both<<<(En + EOn) / 256, 256>>>(ei + En, oei + EOn, pdegs);
    scan_both<<<2, 1024>>>(pdegs, poffs, pcurs);
    fill_both<<<(En + EOn) / 256, 256>>>(ei, oei, pcurs, psrcs);

    const int* poffBig = poffs;
    const int* poffSm  = poffs + Tn + 1;
    const int* psrcBig = psrcs;
    const int* psrcSm  = psrcs + En;
    const size_t WSZ = (size_t)Ln * Dn * Dn;

    for (int i = 0; i < Ln; i++) {
        const size_t wOff = (size_t)i * Dn * Dn;
        const size_t vOff = (size_t)i * Dn;
        const __half* Wr1h = pwh + 0 * WSZ + wOff;
        const __half* Wn1h = pwh + 1 * WSZ + wOff;
        const __half* Wr2h = pwh + 2 * WSZ + wOff;
        const __half* Wn2h = pwh + 3 * WSZ + wOff;
        const __half* Wqh  = pwh + 4 * WSZ + wOff;
        const __half* Wkh  = pwh + 5 * WSZ + wOff;

        // subgraph-level GraphConv (+ fused BN stats; gather zeroes the stat acc)
        gather_half<<<(Tn * 32) / 256, 256>>>(pxh, poffBig, psrcBig, pagg1h, Tn, pacc);
        conv_gemm_f16<<<Tn / 128, 256>>>(pxh, pagg1h, Wr1h, Wn1h, b1 + vOff, pc1, pacc,
                                         nullptr, nullptr, nullptr);

        // attention branch
        if (i == 0) submean_kernel<<<Gn * Sn, 128>>>(x_in, psub, psubh);
        conv_gemm_f16<<<dim3((Gn * Sn) / 128, 2), 256>>>(
            psubh, nullptr, Wqh, nullptr, bq + vOff, pq, nullptr,
            Wkh, bk + vOff, pk);
        attn_kernel<<<Gn, 128>>>(pq, pk, pattn);
        xatten_kernel<<<Gn * Nn, 128>>>(pxh, pattn, pxatth);

        // original-graph GraphConv (+ fused BN stats)
        gather_half<<<(TOn * 32) / 256, 256>>>(pxatth, poffSm, psrcSm, pagg2h, TOn, nullptr);
        conv_gemm_f16<<<TOn / 128, 256>>>(pxatth, pagg2h, Wr2h, Wn2h, b2 + vOff, pc2,
                                          pacc + 256, nullptr, nullptr, nullptr);
        bn_apply2<<<(TOn * Dn) / 256, 256>>>(pc2, pacc + 256, g2 + vOff, be2 + vOff, ph2);

        // x = relu(BN1(c1) + h2 broadcast); BN1 prep + submean + half mirrors fused
        combine_fused<<<Gn * Sn, 128>>>(pc1, pacc, g1 + vOff, be1 + vOff, ph2, px,
                                        psub, psubh, (i < Ln - 1) ? pxh : nullptr);
    }

    head_kernel<<<Gn, 256>>>(psub, Wf1, bf1, Wf2, bf2, pattn, out);
}